// round 11
// baseline (speedup 1.0000x reference)
#include <cuda_runtime.h>

// LSTM_80582176407707 R11: 2 CTAs/SM for latency hiding.
// 256 CTAs x 512 threads (8 warps/SMSP). Each CTA owns 2 hidden units per
// layer (8 gate rows). Thread tile 4 rows x 2 batches (acc[8], <=64 regs via
// __launch_bounds__(512,2)). Per-warp producer flags (16 producers/warp),
// WAR check folded into gate-sum, x-projection filler in the publish window.
// B=32, T=2048, I=256, H=512, O=256.

#define BATCH   32
#define TSTEPS  2048
#define INDIM   256
#define HID     512
#define ODIM    256
#define NCTA    256
#define NTH     512
#define RSTR    528          // 528 mod 32 == 16 -> (rg*RSTR + bg) hits 32 banks

typedef unsigned long long u64;

// h layout: float[buf][q(128)][b(32)][4 comp] == unit (4q+comp) of batch b
__device__ float    g_h0[2][16384];
__device__ float    g_h1[2][16384];
__device__ float4   g_xT[(size_t)TSTEPS * 2048];   // [t][q(64)][b(32)] float4
__device__ unsigned g_flag[NCTA * 32];             // one epoch flag per CTA

__device__ __forceinline__ u64 fma2(u64 a, u64 b, u64 c) {
    u64 d; asm("fma.rn.f32x2 %0, %1, %2, %3;" : "=l"(d) : "l"(a), "l"(b), "l"(c));
    return d;
}
__device__ __forceinline__ u64 pk(float a, float b) {
    u64 r; asm("mov.b64 %0, {%1, %2};" : "=l"(r) : "f"(a), "f"(b)); return r;
}
__device__ __forceinline__ void upk(u64 v, float& lo, float& hi) {
    asm("mov.b64 {%0, %1}, %2;" : "=f"(lo), "=f"(hi) : "l"(v));
}
__device__ __forceinline__ void fence_gpu() {
    asm volatile("fence.acq_rel.gpu;" ::: "memory");
}
__device__ __forceinline__ void st_flag(unsigned* p, unsigned v) {
    asm volatile("st.relaxed.gpu.u32 [%0], %1;" :: "l"(p), "r"(v) : "memory");
}
__device__ __forceinline__ unsigned ld_flag(unsigned* p) {
    unsigned v; asm volatile("ld.relaxed.gpu.u32 %0, [%1];" : "=r"(v) : "l"(p) : "memory");
    return v;
}
__device__ __forceinline__ float sigf(float x) { return 1.0f / (1.0f + __expf(-x)); }

// Per-warp wait: lanes 0..15 poll the 16 producer CTAs of this warp's quads
// (quad q produced by CTAs 2q and 2q+1; warp w consumes quads 8w..8w+7).
__device__ __forceinline__ void warp_wait(int w, int lane, unsigned target) {
    bool done = (lane >= 16);
    unsigned* f = &g_flag[(w * 16 + (lane & 15)) * 32];
    if (!done) done = ((int)(ld_flag(f) - target) >= 0);
    while (!__all_sync(0xffffffffu, done)) {
        if (!done) {
            __nanosleep(24);
            done = ((int)(ld_flag(f) - target) >= 0);
        }
    }
    fence_gpu();
}

// h quad load: lanes (rg broadcast, bg 0..15 consecutive) -> 2 lines/LDG.128
template <bool CG>
__device__ __forceinline__ void ld_h2(const float4* __restrict__ src, int q, int bg,
                                      u64 hlo[2], u64 hhi[2]) {
    #pragma unroll
    for (int j = 0; j < 2; ++j) {
        float4 v = CG ? __ldcg(&src[q * 32 + j * 16 + bg])
                      : __ldg (&src[q * 32 + j * 16 + bg]);
        hlo[j] = pk(v.x, v.y); hhi[j] = pk(v.z, v.w);
    }
}

// one k-quad MMA: 4 weight rows (i) x rg-unit x 2 batches
__device__ __forceinline__ void mma_q2(u64 acc[8], const float4* __restrict__ Ws,
                                       int qbase, int rg,
                                       const u64 hlo[2], const u64 hhi[2]) {
    #pragma unroll
    for (int i = 0; i < 4; ++i) {
        float4 wv = Ws[qbase + i * 2 + rg];
        u64 wl = pk(wv.x, wv.y), wh = pk(wv.z, wv.w);
        #pragma unroll
        for (int j = 0; j < 2; ++j) {
            acc[i * 2 + j] = fma2(hlo[j], wl, acc[i * 2 + j]);
            acc[i * 2 + j] = fma2(hhi[j], wh, acc[i * 2 + j]);
        }
    }
}

// one-time x transpose: x[b][t][i] -> g_xT[t][q][b] float4
__global__ void transpose_x(const float4* __restrict__ x4) {
    int t = blockIdx.x;
    for (int i = threadIdx.x; i < 2048; i += blockDim.x) {
        int q = i >> 5, b = i & 31;
        g_xT[(size_t)t * 2048 + i] = __ldg(&x4[(size_t)b * (TSTEPS * 64) + t * 64 + q]);
    }
}

// store 4x2 accumulator tile to red rows [ROWBASE, ROWBASE+8)
#define STORE_ACC2(ROWBASE)                                                    \
    do {                                                                       \
        _Pragma("unroll")                                                      \
        for (int i = 0; i < 4; ++i)                                            \
            _Pragma("unroll")                                                  \
            for (int j = 0; j < 2; ++j) {                                      \
                float lo, hi; upk(acc[i * 2 + j], lo, hi);                     \
                red[((ROWBASE) + i * 2 + rg) * RSTR + w * 32 + j * 16 + bg]    \
                    = lo + hi;                                                 \
            }                                                                  \
    } while (0)

#define PUBLISH()                                                              \
    do { if (tid == 0) { fence_gpu(); st_flag(&g_flag[r * 32], tgt + 1); }     \
         ++tgt; } while (0)

// WAR-slack check: all CTAs finished the PREVIOUS superstep. tid<256 only.
#define FULL_CHECK(TARGET)                                                     \
    do { while ((int)(ld_flag(&g_flag[tid * 32]) - (TARGET)) < 0)              \
             __nanosleep(32); } while (0)

__global__ __launch_bounds__(NTH, 2) void lstm_persistent_kernel(
    const float* __restrict__ x,
    const float* __restrict__ Wih0, const float* __restrict__ Whh0,
    const float* __restrict__ bih0, const float* __restrict__ bhh0,
    const float* __restrict__ Wih1, const float* __restrict__ Whh1,
    const float* __restrict__ bih1, const float* __restrict__ bhh1,
    const float* __restrict__ fcw,  const float* __restrict__ fcb,
    float* __restrict__ out)
{
    extern __shared__ float4 smemf4[];
    float4* W0s   = smemf4;                // [192 q][8 l] (x 0-63 | h0 64-191)
    float4* W1s   = W0s + 192 * 8;         // [256 q][8 l] (h0 0-127 | h1 128-255)
    float*  red   = (float*)(W1s + 256 * 8);   // [24 rows][RSTR]
                                           // rows 0-7: L1, 8-15: L0-h, 16-23: L0-x
    float*  gates = red + 24 * RSTR;       // [16 rows][32 b] (0-7 L1, 8-15 L0)
    float*  b1s   = gates + 512;           // [8]
    float*  b0s   = b1s + 8;               // [8]

    const int tid  = threadIdx.x;
    const int r    = blockIdx.x;           // CTA owns units 2r, 2r+1 per layer
    const int w    = tid >> 5;             // k-chunk warp 0..15
    const int lane = tid & 31;
    const int rg   = lane >> 4;            // unit group 0..1
    const int bg   = lane & 15;            // batch group 0..15

    unsigned tgt = ld_flag(&g_flag[r * 32]);   // epoch base (persists across replays)

    // ---- weights into SMEM, [quad][8 rows] layout; row l = gate*2 + unit ----
    for (int idx = tid; idx < 192 * 8; idx += NTH) {
        int q = idx >> 3, l = idx & 7;
        int grow = ((l >> 1) << 9) + (r << 1) + (l & 1);
        int k0 = q << 2;
        const float* p = (k0 < INDIM) ? (Wih0 + grow * INDIM + k0)
                                      : (Whh0 + grow * HID + (k0 - INDIM));
        W0s[idx] = make_float4(p[0], p[1], p[2], p[3]);
    }
    for (int idx = tid; idx < 256 * 8; idx += NTH) {
        int q = idx >> 3, l = idx & 7;
        int grow = ((l >> 1) << 9) + (r << 1) + (l & 1);
        int k0 = q << 2;
        const float* p = (k0 < HID) ? (Wih1 + grow * HID + k0)
                                    : (Whh1 + grow * HID + (k0 - HID));
        W1s[idx] = make_float4(p[0], p[1], p[2], p[3]);
    }
    if (tid < 8) {
        int grow = ((tid >> 1) << 9) + (r << 1) + (tid & 1);
        b0s[tid] = bih0[grow] + bhh0[grow];
        b1s[tid] = bih1[grow] + bhh1[grow];
    }
    // zero h1(-1) buffer 0, own slice (units 2r, 2r+1, all batches)
    if (tid < 64) {
        int uu = tid >> 5, b = tid & 31;
        g_h1[0][(r >> 1) * 128 + b * 4 + 2 * (r & 1) + uu] = 0.0f;
    }
    __syncthreads();

    float c0 = 0.0f, c1 = 0.0f;            // c1 in tid<64, c0 in tid 64..127
    u64 hlo[2], hhi[2];
    u64 acc[8];

    const int cuu  = (tid >> 5) & 1;       // cell unit (0..1) for cell threads
    const int cb   = tid & 31;
    const int hidx = (r >> 1) * 128 + 2 * (r & 1) + cuu;  // + b*4

    // =============== PROLOGUE: layer0(t=0) (h0(-1)=0 -> x part only) ========
    {
        #pragma unroll
        for (int n = 0; n < 8; ++n) acc[n] = 0ull;
        #pragma unroll
        for (int v = 0; v < 4; ++v) {
            int q = w * 4 + v;
            ld_h2<false>(g_xT, q, bg, hlo, hhi);     // t = 0
            mma_q2(acc, W0s, q * 8, rg, hlo, hhi);
        }
        STORE_ACC2(16);
        __syncthreads();
        if (tid < 256) {
            int row = tid >> 5, b = tid & 31;        // row 0..7 -> L0 gates
            float s0 = b0s[row];
            #pragma unroll
            for (int k = 0; k < 16; ++k) s0 += red[(16 + row) * RSTR + k * 32 + b];
            gates[(8 + row) * 32 + b] = s0;
        }
        __syncthreads();
        if (tid >= 64 && tid < 128) {                // L0 cells
            float gi = sigf(gates[(8 + cuu) * 32 + cb]);
            float gf = sigf(gates[(10 + cuu) * 32 + cb]);
            float gg = tanhf(gates[(12 + cuu) * 32 + cb]);
            float go = sigf(gates[(14 + cuu) * 32 + cb]);
            c0 = gf * c0 + gi * gg;
            g_h0[0][hidx + cb * 4] = go * tanhf(c0);
        }
        __syncthreads();
        PUBLISH();                         // flag = base+1: h0(0), h1(-1) ready
        // hoisted x(1) projection -> red rows 16-23 (publish-window filler)
        {
            #pragma unroll
            for (int n = 0; n < 8; ++n) acc[n] = 0ull;
            const float4* xt = g_xT + 2048;          // t = 1
            #pragma unroll
            for (int v = 0; v < 4; ++v) {
                int q = w * 4 + v;
                ld_h2<false>(xt, q, bg, hlo, hhi);
                mma_q2(acc, W0s, q * 8, rg, hlo, hhi);
            }
            STORE_ACC2(16);
        }
    }

    // =============== MAIN LOOP: superstep s = layer1(s) + layer0(s+1) =======
    #pragma unroll 1
    for (int s = 0; s < TSTEPS - 1; ++s) {
        const int p = s & 1;
        const float4* h0p = (const float4*)g_h0[p];
        const float4* h1p = (const float4*)g_h1[p];

        warp_wait(w, lane, tgt);           // this warp's 16 producers only

        // ---- pass 1: layer1 gates (K=1024: h0 | h1) ----
        #pragma unroll
        for (int n = 0; n < 8; ++n) acc[n] = 0ull;
        #pragma unroll 2
        for (int u = 0; u < 8; ++u) {
            int q = w * 8 + u;
            ld_h2<true>(h0p, q, bg, hlo, hhi);
            mma_q2(acc, W1s, q * 8, rg, hlo, hhi);
        }
        #pragma unroll 2
        for (int u = 0; u < 8; ++u) {
            int q = w * 8 + u;
            ld_h2<true>(h1p, q, bg, hlo, hhi);
            mma_q2(acc, W1s, (128 + q) * 8, rg, hlo, hhi);
        }
        STORE_ACC2(0);

        // ---- pass 0: layer0(s+1) h-part (K=512; x-part precomputed) ----
        #pragma unroll
        for (int n = 0; n < 8; ++n) acc[n] = 0ull;
        #pragma unroll 2
        for (int u = 0; u < 8; ++u) {
            int q = w * 8 + u;
            ld_h2<true>(h0p, q, bg, hlo, hhi);
            mma_q2(acc, W0s, (64 + q) * 8, rg, hlo, hhi);
        }
        STORE_ACC2(8);
        __syncthreads();

        // ---- gate sums (rows 0-7 L1, 8-15 L0) + WAR slack check ----
        if (tid < NTH) {
            int row = tid >> 5, b = tid & 31;        // row 0..15
            if (row < 8) {
                float s1 = b1s[row];
                #pragma unroll
                for (int k = 0; k < 16; ++k) s1 += red[row * RSTR + k * 32 + b];
                gates[row * 32 + b] = s1;
            } else {
                int r0 = row - 8;
                float s0 = b0s[r0];
                #pragma unroll
                for (int k = 0; k < 16; ++k)
                    s0 += red[row * RSTR + k * 32 + b]
                        + red[(row + 8) * RSTR + k * 32 + b];
                gates[row * 32 + b] = s0;
            }
            if (tid < NCTA) FULL_CHECK(tgt);
        }
        __syncthreads();

        // ---- cells (tid<64: L1 -> c1; tid 64..127: L0 -> c0) ----
        if (tid < 128) {
            int L = tid >> 6;
            int gb = L * 8;
            float gi = sigf(gates[(gb + cuu) * 32 + cb]);
            float gf = sigf(gates[(gb + 2 + cuu) * 32 + cb]);
            float gg = tanhf(gates[(gb + 4 + cuu) * 32 + cb]);
            float go = sigf(gates[(gb + 6 + cuu) * 32 + cb]);
            if (L == 0) {                  // layer1 -> h1(s)
                c1 = gf * c1 + gi * gg;
                g_h1[1 - p][hidx + cb * 4] = go * tanhf(c1);
            } else {                       // layer0 -> h0(s+1)
                c0 = gf * c0 + gi * gg;
                g_h0[1 - p][hidx + cb * 4] = go * tanhf(c0);
            }
        }
        __syncthreads();
        PUBLISH();

        // ---- hoisted x(s+2) projection (publish-window filler) ----
        if (s < TSTEPS - 2) {
            #pragma unroll
            for (int n = 0; n < 8; ++n) acc[n] = 0ull;
            const float4* xt = g_xT + (size_t)(s + 2) * 2048;
            #pragma unroll
            for (int v = 0; v < 4; ++v) {
                int q = w * 4 + v;
                ld_h2<false>(xt, q, bg, hlo, hhi);
                mma_q2(acc, W0s, q * 8, rg, hlo, hhi);
            }
            STORE_ACC2(16);
        }
    }

    // =============== EPILOGUE: layer1(t=2047) ===============
    {
        const int p = (TSTEPS - 1) & 1;    // 1
        const float4* h0p = (const float4*)g_h0[p];
        const float4* h1p = (const float4*)g_h1[p];

        warp_wait(w, lane, tgt);

        #pragma unroll
        for (int n = 0; n < 8; ++n) acc[n] = 0ull;
        #pragma unroll 2
        for (int u = 0; u < 8; ++u) {
            int q = w * 8 + u;
            ld_h2<true>(h0p, q, bg, hlo, hhi);
            mma_q2(acc, W1s, q * 8, rg, hlo, hhi);
        }
        #pragma unroll 2
        for (int u = 0; u < 8; ++u) {
            int q = w * 8 + u;
            ld_h2<true>(h1p, q, bg, hlo, hhi);
            mma_q2(acc, W1s, (128 + q) * 8, rg, hlo, hhi);
        }
        STORE_ACC2(0);
        __syncthreads();
        if (tid < 256) {
            int row = tid >> 5, b = tid & 31;        // rows 0..7 (L1)
            float s1 = b1s[row];
            #pragma unroll
            for (int k = 0; k < 16; ++k) s1 += red[row * RSTR + k * 32 + b];
            gates[row * 32 + b] = s1;
            FULL_CHECK(tgt);
        }
        __syncthreads();
        if (tid < 64) {                    // L1 cells
            float gi = sigf(gates[(cuu) * 32 + cb]);
            float gf = sigf(gates[(2 + cuu) * 32 + cb]);
            float gg = tanhf(gates[(4 + cuu) * 32 + cb]);
            float go = sigf(gates[(6 + cuu) * 32 + cb]);
            c1 = gf * c1 + gi * gg;
            g_h1[1 - p][hidx + cb * 4] = go * tanhf(c1);  // -> buffer 0
        }
        __syncthreads();
        PUBLISH();
    }

    // =============== FINAL FC (needs ALL CTAs' final h1) ===============
    if (tid < NCTA) FULL_CHECK(tgt);
    fence_gpu();
    __syncthreads();
    if (tid < 32) {                        // out[b][r] for b = tid
        int b = tid;
        float accf = __ldg(&fcb[r]);
        const float4* h1f = (const float4*)g_h1[0];
        const float4* w4  = (const float4*)(fcw + r * HID);
        #pragma unroll 4
        for (int q = 0; q < 128; ++q) {
            float4 hv = __ldcg(&h1f[q * 32 + b]);   // units 4q..4q+3 of batch b
            float4 wv = __ldg(&w4[q]);
            accf = fmaf(hv.x, wv.x, accf); accf = fmaf(hv.y, wv.y, accf);
            accf = fmaf(hv.z, wv.z, accf); accf = fmaf(hv.w, wv.w, accf);
        }
        out[b * ODIM + r] = accf;
    }
}

extern "C" void kernel_launch(void* const* d_in, const int* in_sizes, int n_in,
                              void* d_out, int out_size) {
    const float* x    = (const float*)d_in[0];
    const float* Wih0 = (const float*)d_in[1];
    const float* Whh0 = (const float*)d_in[2];
    const float* bih0 = (const float*)d_in[3];
    const float* bhh0 = (const float*)d_in[4];
    const float* Wih1 = (const float*)d_in[5];
    const float* Whh1 = (const float*)d_in[6];
    const float* bih1 = (const float*)d_in[7];
    const float* bhh1 = (const float*)d_in[8];
    const float* fcw  = (const float*)d_in[9];
    const float* fcb  = (const float*)d_in[10];
    float* out = (float*)d_out;

    transpose_x<<<TSTEPS, 256>>>((const float4*)x);

    // (192*8 + 256*8) f4 + (24*RSTR + 16*32 + 16) f  = 57344 + 52800 = 110144 B
    const int smem_bytes = (192 * 8 + 256 * 8) * 16 +
                           (24 * RSTR + 16 * 32 + 16) * 4;
    cudaFuncSetAttribute(lstm_persistent_kernel,
                         cudaFuncAttributeMaxDynamicSharedMemorySize, smem_bytes);
    lstm_persistent_kernel<<<NCTA, NTH, smem_bytes>>>(
        x, Wih0, Whh0, bih0, bhh0, Wih1, Whh1, bih1, bhh1, fcw, fcb, out);
}

// round 13
// speedup vs baseline: 1.2893x; 1.2893x over previous
#include <cuda_runtime.h>

// LSTM_80582176407707 R12: exact R5 structure (best measured, 17.91ms) with ONE
// change: h loads use ld.global.ca (L1-cached, coherent) instead of __ldcg.
// The barrier's fence.acq_rel.gpu emits CCTL.IVALL (L1 flush) each superstep,
// making L1-cached reads of cross-SM h legal; pass 0 then re-reads the h0
// quads pass 1 just warmed -> L1 hits (~39cyc) instead of L2 (~240cyc).
// B=32, T=2048, I=256, H=512, O=256. 128 CTAs x 512 threads, 1 CTA/SM.

#define BATCH   32
#define TSTEPS  2048
#define INDIM   256
#define HID     512
#define ODIM    256
#define NCTA    128
#define NTH     512
#define RSTR    520          // red row stride (floats): rows 8 banks apart

typedef unsigned long long u64;

// h layout: float[buf][q(128)][b(32)][4 comp]  == unit (4q+comp) of batch b
__device__ float    g_h0[2][16384];
__device__ float    g_h1[2][16384];
__device__ float4   g_xT[(size_t)TSTEPS * 2048];   // [t][q(64)][b(32)] float4
__device__ unsigned g_flag[NCTA * 32];

__device__ __forceinline__ u64 fma2(u64 a, u64 b, u64 c) {
    u64 d; asm("fma.rn.f32x2 %0, %1, %2, %3;" : "=l"(d) : "l"(a), "l"(b), "l"(c));
    return d;
}
__device__ __forceinline__ u64 pk(float a, float b) {
    u64 r; asm("mov.b64 %0, {%1, %2};" : "=l"(r) : "f"(a), "f"(b)); return r;
}
__device__ __forceinline__ void upk(u64 v, float& lo, float& hi) {
    asm("mov.b64 {%0, %1}, %2;" : "=f"(lo), "=f"(hi) : "l"(v));
}
__device__ __forceinline__ void fence_gpu() {
    asm volatile("fence.acq_rel.gpu;" ::: "memory");
}
__device__ __forceinline__ void st_flag(unsigned* p, unsigned v) {
    asm volatile("st.relaxed.gpu.u32 [%0], %1;" :: "l"(p), "r"(v) : "memory");
}
__device__ __forceinline__ unsigned ld_flag(unsigned* p) {
    unsigned v; asm volatile("ld.relaxed.gpu.u32 %0, [%1];" : "=r"(v) : "l"(p) : "memory");
    return v;
}
__device__ __forceinline__ float sigf(float x) { return 1.0f / (1.0f + __expf(-x)); }

// coherent L1-cached vector load (NOT the nc/texture path __ldg uses)
__device__ __forceinline__ float4 ldca4(const float4* p) {
    float4 v;
    asm volatile("ld.global.ca.v4.f32 {%0, %1, %2, %3}, [%4];"
                 : "=f"(v.x), "=f"(v.y), "=f"(v.z), "=f"(v.w) : "l"(p));
    return v;
}

// h quad load: lanes (rg broadcast, bg 0..7 consecutive) -> 1 line per LDG.128
// CG=true: mutable h (L1-cached coherent). CG=false: immutable x (__ldg/nc).
template <bool CG>
__device__ __forceinline__ void ld_h(const float4* __restrict__ src, int q, int bg,
                                     u64 hlo[4], u64 hhi[4]) {
    #pragma unroll
    for (int j = 0; j < 4; ++j) {
        float4 v = CG ? ldca4(&src[q * 32 + j * 8 + bg])
                      : __ldg (&src[q * 32 + j * 8 + bg]);
        hlo[j] = pk(v.x, v.y); hhi[j] = pk(v.z, v.w);
    }
}

// one k-quad MMA: 4 weight rows (lanes rg distinct, conflict-free) x 4 batches
__device__ __forceinline__ void mma_q(u64 acc[16], const float4* __restrict__ Ws,
                                      int qbase, int rg,
                                      const u64 hlo[4], const u64 hhi[4]) {
    #pragma unroll
    for (int i = 0; i < 4; ++i) {
        float4 wv = Ws[qbase + i * 4 + rg];
        u64 wl = pk(wv.x, wv.y), wh = pk(wv.z, wv.w);
        #pragma unroll
        for (int j = 0; j < 4; ++j) {
            acc[i * 4 + j] = fma2(hlo[j], wl, acc[i * 4 + j]);
            acc[i * 4 + j] = fma2(hhi[j], wh, acc[i * 4 + j]);
        }
    }
}

// one-time x transpose: x[b][t][i] -> g_xT[t][q][b] float4
__global__ void transpose_x(const float4* __restrict__ x4) {
    int t = blockIdx.x;
    for (int i = threadIdx.x; i < 2048; i += blockDim.x) {
        int q = i >> 5, b = i & 31;
        g_xT[(size_t)t * 2048 + i] = __ldg(&x4[(size_t)b * (TSTEPS * 64) + t * 64 + q]);
    }
}

// store 4x4 accumulator tile to red rows [rowbase, rowbase+16)
#define STORE_ACC(ROWBASE)                                                     \
    do {                                                                       \
        _Pragma("unroll")                                                      \
        for (int i = 0; i < 4; ++i)                                            \
            _Pragma("unroll")                                                  \
            for (int j = 0; j < 4; ++j) {                                      \
                float lo, hi; upk(acc[i * 4 + j], lo, hi);                     \
                red[((ROWBASE) + i * 4 + rg) * RSTR + w * 32 + j * 8 + bg]     \
                    = lo + hi;                                                 \
            }                                                                  \
    } while (0)

#define BARRIER_PUBLISH()                                                      \
    do { if (tid == 0) { fence_gpu(); st_flag(&g_flag[r * 32], tgt + 1); }     \
         ++tgt; } while (0)

#define BARRIER_POLL()                                                         \
    do { if (tid < NCTA) {                                                     \
             while ((int)(ld_flag(&g_flag[tid * 32]) - tgt) < 0)               \
                 __nanosleep(32);                                              \
             fence_gpu();                                                      \
         }                                                                     \
         __syncthreads(); } while (0)

__global__ __launch_bounds__(NTH, 1) void lstm_persistent_kernel(
    const float* __restrict__ x,
    const float* __restrict__ Wih0, const float* __restrict__ Whh0,
    const float* __restrict__ bih0, const float* __restrict__ bhh0,
    const float* __restrict__ Wih1, const float* __restrict__ Whh1,
    const float* __restrict__ bih1, const float* __restrict__ bhh1,
    const float* __restrict__ fcw,  const float* __restrict__ fcb,
    float* __restrict__ out)
{
    extern __shared__ float4 smemf4[];
    float4* W0s   = smemf4;                // [192 q][16 l]  (x 0-63 | h 64-191)
    float4* W1s   = W0s + 192 * 16;        // [256 q][16 l]
    float*  red   = (float*)(W1s + 256 * 16);  // [48 rows][RSTR]
    float*  gates = red + 48 * RSTR;       // [32 rows][32 b]
    float*  b1s   = gates + 1024;          // [16]
    float*  b0s   = b1s + 16;              // [16]

    const int tid  = threadIdx.x;
    const int r    = blockIdx.x;
    const int w    = tid >> 5;             // k-chunk warp 0..15
    const int lane = tid & 31;
    const int rg   = lane >> 3;            // row group 0..3
    const int bg   = lane & 7;             // batch group 0..7

    unsigned tgt = ld_flag(&g_flag[r * 32]);   // epoch base

    // ---- weights into SMEM, [quad][row] layout ----
    for (int idx = tid; idx < 192 * 16; idx += NTH) {
        int q = idx >> 4, l = idx & 15;
        int grow = ((l >> 2) << 9) + (r << 2) + (l & 3);
        int k0 = q << 2;
        const float* p = (k0 < INDIM) ? (Wih0 + grow * INDIM + k0)
                                      : (Whh0 + grow * HID + (k0 - INDIM));
        W0s[idx] = make_float4(p[0], p[1], p[2], p[3]);
    }
    for (int idx = tid; idx < 256 * 16; idx += NTH) {
        int q = idx >> 4, l = idx & 15;
        int grow = ((l >> 2) << 9) + (r << 2) + (l & 3);
        int k0 = q << 2;
        const float* p = (k0 < HID) ? (Wih1 + grow * HID + k0)
                                    : (Whh1 + grow * HID + (k0 - HID));
        W1s[idx] = make_float4(p[0], p[1], p[2], p[3]);
    }
    if (tid < 16) {
        int grow = ((tid >> 2) << 9) + (r << 2) + (tid & 3);
        b0s[tid] = bih0[grow] + bhh0[grow];
        b1s[tid] = bih1[grow] + bhh1[grow];
    }
    if (tid < 128) g_h1[0][r * 128 + tid] = 0.0f;   // h1(-1) = 0 (own slice)
    __syncthreads();

    float c0 = 0.0f, c1 = 0.0f;            // c1 in tid<128, c0 in tid 128..255
    u64 hlo[4], hhi[4];
    u64 acc[16];

    // =============== PROLOGUE: layer0(t=0) (h0(-1)=0 -> x part only) ========
    {
        #pragma unroll
        for (int n = 0; n < 16; ++n) acc[n] = 0ull;
        #pragma unroll
        for (int v = 0; v < 4; ++v) {
            int q = w * 4 + v;
            ld_h<false>(g_xT, q, bg, hlo, hhi);      // t = 0
            mma_q(acc, W0s, q * 16, rg, hlo, hhi);
        }
        STORE_ACC(16);
        __syncthreads();
        {
            int row = tid >> 5, b = tid & 31;
            float s0 = b0s[row];
            #pragma unroll
            for (int k = 0; k < 16; ++k) s0 += red[(16 + row) * RSTR + k * 32 + b];
            gates[(16 + row) * 32 + b] = s0;
        }
        __syncthreads();
        if (tid >= 128 && tid < 256) {
            int u = (tid >> 5) & 3, b2 = tid & 31;
            float gi = sigf(gates[(16 + u) * 32 + b2]);
            float gf = sigf(gates[(20 + u) * 32 + b2]);
            float gg = tanhf(gates[(24 + u) * 32 + b2]);
            float go = sigf(gates[(28 + u) * 32 + b2]);
            c0 = gf * c0 + gi * gg;
            g_h0[0][r * 128 + b2 * 4 + u] = go * tanhf(c0);
        }
        __syncthreads();
        BARRIER_PUBLISH();
        // hoisted: x(1) projection partials -> red rows 32-47 (barrier filler)
        {
            #pragma unroll
            for (int n = 0; n < 16; ++n) acc[n] = 0ull;
            const float4* xt = g_xT + 2048;          // t = 1
            #pragma unroll
            for (int v = 0; v < 4; ++v) {
                int q = w * 4 + v;
                ld_h<false>(xt, q, bg, hlo, hhi);
                mma_q(acc, W0s, q * 16, rg, hlo, hhi);
            }
            STORE_ACC(32);
        }
        BARRIER_POLL();
    }

    // =============== MAIN LOOP: superstep s = layer1(s) + layer0(s+1) =======
    #pragma unroll 1
    for (int s = 0; s < TSTEPS - 1; ++s) {
        const int p = s & 1;
        const float4* h0p = (const float4*)g_h0[p];
        const float4* h1p = (const float4*)g_h1[p];

        // ---- pass 1: layer1 gates (K=1024: h0 | h1) ----
        #pragma unroll
        for (int n = 0; n < 16; ++n) acc[n] = 0ull;
        #pragma unroll 2
        for (int u = 0; u < 8; ++u) {
            int q = w * 8 + u;
            ld_h<true>(h0p, q, bg, hlo, hhi);        // warms L1 for pass 0
            mma_q(acc, W1s, q * 16, rg, hlo, hhi);
        }
        #pragma unroll 2
        for (int u = 0; u < 8; ++u) {
            int q = w * 8 + u;
            ld_h<true>(h1p, q, bg, hlo, hhi);
            mma_q(acc, W1s, (128 + q) * 16, rg, hlo, hhi);
        }
        STORE_ACC(0);

        // ---- pass 0: layer0(s+1) h-part (K=512; h0 quads now L1-hot) ----
        #pragma unroll
        for (int n = 0; n < 16; ++n) acc[n] = 0ull;
        #pragma unroll 2
        for (int u = 0; u < 8; ++u) {
            int q = w * 8 + u;
            ld_h<true>(h0p, q, bg, hlo, hhi);
            mma_q(acc, W0s, (64 + q) * 16, rg, hlo, hhi);
        }
        STORE_ACC(16);
        __syncthreads();

        // ---- gate sums ----
        {
            int row = tid >> 5, b = tid & 31;
            float s1 = b1s[row], s0 = b0s[row];
            #pragma unroll
            for (int k = 0; k < 16; ++k) {
                s1 += red[row * RSTR + k * 32 + b];
                s0 += red[(16 + row) * RSTR + k * 32 + b]
                    + red[(32 + row) * RSTR + k * 32 + b];
            }
            gates[row * 32 + b]        = s1;
            gates[(16 + row) * 32 + b] = s0;
        }
        __syncthreads();

        // ---- cells ----
        if (tid < 256) {
            int L = tid >> 7, u = (tid >> 5) & 3, b = tid & 31;
            int ro = L * 16;
            float gi = sigf(gates[(ro + u) * 32 + b]);
            float gf = sigf(gates[(ro + 4 + u) * 32 + b]);
            float gg = tanhf(gates[(ro + 8 + u) * 32 + b]);
            float go = sigf(gates[(ro + 12 + u) * 32 + b]);
            if (L == 0) {                  // layer1 -> h1(s)
                c1 = gf * c1 + gi * gg;
                g_h1[1 - p][r * 128 + b * 4 + u] = go * tanhf(c1);
            } else {                       // layer0 -> h0(s+1)
                c0 = gf * c0 + gi * gg;
                g_h0[1 - p][r * 128 + b * 4 + u] = go * tanhf(c0);
            }
        }
        __syncthreads();
        BARRIER_PUBLISH();

        // ---- hoisted x(s+2) projection during barrier wait ----
        if (s < TSTEPS - 2) {
            #pragma unroll
            for (int n = 0; n < 16; ++n) acc[n] = 0ull;
            const float4* xt = g_xT + (size_t)(s + 2) * 2048;
            #pragma unroll
            for (int v = 0; v < 4; ++v) {
                int q = w * 4 + v;
                ld_h<false>(xt, q, bg, hlo, hhi);
                mma_q(acc, W0s, q * 16, rg, hlo, hhi);
            }
            STORE_ACC(32);
        }
        BARRIER_POLL();
    }

    // =============== EPILOGUE: layer1(t=2047) ===============
    {
        const int p = (TSTEPS - 1) & 1;    // 1
        const float4* h0p = (const float4*)g_h0[p];
        const float4* h1p = (const float4*)g_h1[p];
        #pragma unroll
        for (int n = 0; n < 16; ++n) acc[n] = 0ull;
        #pragma unroll 2
        for (int u = 0; u < 8; ++u) {
            int q = w * 8 + u;
            ld_h<true>(h0p, q, bg, hlo, hhi);
            mma_q(acc, W1s, q * 16, rg, hlo, hhi);
        }
        #pragma unroll 2
        for (int u = 0; u < 8; ++u) {
            int q = w * 8 + u;
            ld_h<true>(h1p, q, bg, hlo, hhi);
            mma_q(acc, W1s, (128 + q) * 16, rg, hlo, hhi);
        }
        STORE_ACC(0);
        __syncthreads();
        {
            int row = tid >> 5, b = tid & 31;
            float s1 = b1s[row];
            #pragma unroll
            for (int k = 0; k < 16; ++k) s1 += red[row * RSTR + k * 32 + b];
            gates[row * 32 + b] = s1;
        }
        __syncthreads();
        if (tid < 128) {
            int u = (tid >> 5) & 3, b = tid & 31;
            float gi = sigf(gates[(u) * 32 + b]);
            float gf = sigf(gates[(4 + u) * 32 + b]);
            float gg = tanhf(gates[(8 + u) * 32 + b]);
            float go = sigf(gates[(12 + u) * 32 + b]);
            c1 = gf * c1 + gi * gg;
            g_h1[1 - p][r * 128 + b * 4 + u] = go * tanhf(c1);  // -> buffer 0
        }
        __syncthreads();
        BARRIER_PUBLISH();
        BARRIER_POLL();
    }

    // =============== FINAL FC ===============
    if (tid < 64) {
        int oo = tid >> 5, b = tid & 31;
        int o = (r << 1) + oo;
        float accf = __ldg(&fcb[o]);
        const float4* h1f = (const float4*)g_h1[0];
        const float4* w4  = (const float4*)(fcw + o * HID);
        #pragma unroll 4
        for (int q = 0; q < 128; ++q) {
            float4 hv = ldca4(&h1f[q * 32 + b]);
            float4 wv = __ldg(&w4[q]);
            accf = fmaf(hv.x, wv.x, accf); accf = fmaf(hv.y, wv.y, accf);
            accf = fmaf(hv.z, wv.z, accf); accf = fmaf(hv.w, wv.w, accf);
        }
        out[b * ODIM + o] = accf;
    }
}

extern "C" void kernel_launch(void* const* d_in, const int* in_sizes, int n_in,
                              void* d_out, int out_size) {
    const float* x    = (const float*)d_in[0];
    const float* Wih0 = (const float*)d_in[1];
    const float* Whh0 = (const float*)d_in[2];
    const float* bih0 = (const float*)d_in[3];
    const float* bhh0 = (const float*)d_in[4];
    const float* Wih1 = (const float*)d_in[5];
    const float* Whh1 = (const float*)d_in[6];
    const float* bih1 = (const float*)d_in[7];
    const float* bhh1 = (const float*)d_in[8];
    const float* fcw  = (const float*)d_in[9];
    const float* fcb  = (const float*)d_in[10];
    float* out = (float*)d_out;

    transpose_x<<<TSTEPS, 256>>>((const float4*)x);

    const int smem_bytes = (192 * 16 + 256 * 16) * 16 +
                           (48 * RSTR + 1024 + 32) * 4;   // 218752 B
    cudaFuncSetAttribute(lstm_persistent_kernel,
                         cudaFuncAttributeMaxDynamicSharedMemorySize, smem_bytes);
    lstm_persistent_kernel<<<NCTA, NTH, smem_bytes>>>(
        x, Wih0, Whh0, bih0, bhh0, Wih1, Whh1, bih1, bhh1, fcw, fcb, out);
}